// round 7
// baseline (speedup 1.0000x reference)
#include <cuda_runtime.h>
#include <cuda_bf16.h>
#include <cstdint>

// ---------------------------------------------------------------------------
// Problem shape
// ---------------------------------------------------------------------------
#define N_BATCH 32
#define CH      64
#define HH      112
#define WW      112
#define PIX     (HH*WW)              // 12544
#define NX      (N_BATCH*CH*PIX)     // 25,690,112
#define NWELEM  (64*64*3*3)          // 36,864
#define TILES_PER_IMG (PIX/128)      // 98
#define NTILES  (N_BATCH*TILES_PER_IMG)  // 3136
#define NGROUPS ((NX + 35) / 36)     // 713,615

__device__ __align__(16) __nv_bfloat16 g_xt[NX];       // quantized x, NHWC
__device__ __align__(16) __nv_bfloat16 g_wq[NWELEM];   // quantized w, OIHW
__device__ __align__(16) __nv_bfloat16 g_wk[9*64*64];  // [k][co][ci]
__device__ __align__(16) float2        g_scale[NGROUPS]; // {scl, inv} per group

#define SW128(off) ((off) ^ (((off) >> 3) & 0x70))

// ---------------------------------------------------------------------------
// Pass 1 (x): per-group scale computation only.
// Block owns 2304 float4 = 9216 elems = 256 groups (4 | 36 so a float4 never
// crosses a group boundary). Writes {scl, inv} per group.
// ---------------------------------------------------------------------------
__global__ __launch_bounds__(256)
void bfp_scale_kernel(const float4* __restrict__ src, int n4, long ngroups,
                      float2* __restrict__ scale) {
    __shared__ float sMax[2304];
    const int tid = threadIdx.x;
    const long base = (long)blockIdx.x * 2304;

    #pragma unroll
    for (int r = 0; r < 9; ++r) {
        long j = base + r * 256 + tid;
        float4 x = make_float4(0.f, 0.f, 0.f, 0.f);
        if (j < n4) x = src[j];
        sMax[r * 256 + tid] =
            fmaxf(fmaxf(fabsf(x.x), fabsf(x.y)), fmaxf(fabsf(x.z), fabsf(x.w)));
    }
    __syncthreads();
    long g = (long)blockIdx.x * 256 + tid;
    if (g < ngroups) {
        float m = sMax[tid * 9];
        #pragma unroll
        for (int i = 1; i < 9; ++i) m = fmaxf(m, sMax[tid * 9 + i]);
        float scl = 0.f, inv = 0.f;
        if (m > 0.f) {
            float e = floorf(log2f(m));
            scl = exp2f(e - 7.f);    // exact powers of two
            inv = exp2f(7.f - e);
        }
        scale[g] = make_float2(scl, inv);
    }
}

// ---------------------------------------------------------------------------
// Quantize with stores (used for the small weight tensor only)
// ---------------------------------------------------------------------------
__global__ __launch_bounds__(256)
void bfp_quant_store_kernel(const float4* __restrict__ src, int n4,
                            uint2* __restrict__ dst) {
    __shared__ float sMax[2304];
    __shared__ float sScl[256];
    __shared__ float sInv[256];
    const int tid = threadIdx.x;
    const long base = (long)blockIdx.x * 2304;

    float4 v[9];
    #pragma unroll
    for (int r = 0; r < 9; ++r) {
        long j = base + r * 256 + tid;
        float4 x = make_float4(0.f, 0.f, 0.f, 0.f);
        if (j < n4) x = src[j];
        v[r] = x;
        sMax[r * 256 + tid] =
            fmaxf(fmaxf(fabsf(x.x), fabsf(x.y)), fmaxf(fabsf(x.z), fabsf(x.w)));
    }
    __syncthreads();
    {
        float m = sMax[tid * 9];
        #pragma unroll
        for (int i = 1; i < 9; ++i) m = fmaxf(m, sMax[tid * 9 + i]);
        float scl = 0.f, inv = 0.f;
        if (m > 0.f) {
            float e = floorf(log2f(m));
            scl = exp2f(e - 7.f);
            inv = exp2f(7.f - e);
        }
        sScl[tid] = scl;
        sInv[tid] = inv;
    }
    __syncthreads();
    #pragma unroll
    for (int r = 0; r < 9; ++r) {
        long j = base + r * 256 + tid;
        if (j >= n4) continue;
        int g = (r * 256 + tid) / 9;
        float scl = sScl[g], inv = sInv[g];
        float4 x = v[r];
        __nv_bfloat162 lo = __floats2bfloat162_rn(rintf(x.x * inv) * scl,
                                                  rintf(x.y * inv) * scl);
        __nv_bfloat162 hi = __floats2bfloat162_rn(rintf(x.z * inv) * scl,
                                                  rintf(x.w * inv) * scl);
        uint2 o;
        o.x = *(uint32_t*)&lo;
        o.y = *(uint32_t*)&hi;
        dst[j] = o;
    }
}

// ---------------------------------------------------------------------------
// Pass 2 (x): fused quantize + NCHW->NHWC transpose.
// Block = [64 ci][64 pix] of one image. Reads fp32 NCHW + group scales,
// quantizes, transposes via smem, writes NHWC bf16.
// NOTE: smem stores are scalar bf16 (stride 65 is odd -> no 4B vector stores).
// ---------------------------------------------------------------------------
__global__ __launch_bounds__(256)
void quant_transpose_kernel(const float4* __restrict__ x,
                            const float2* __restrict__ scale,
                            __nv_bfloat16* __restrict__ dst) {
    __shared__ __nv_bfloat16 s[64 * 65];
    const int tid = threadIdx.x;
    const int n   = blockIdx.y;
    const int p0  = blockIdx.x * 64;     // multiple of 64

    #pragma unroll
    for (int it = 0; it < 4; ++it) {
        int idx = it * 256 + tid;          // [0,1024)
        int ci = idx >> 4;                 // 64 rows
        int c  = idx & 15;                 // float4 col within 64-pix window
        long f4 = (long)(n * 64 + ci) * (PIX / 4) + (p0 >> 2) + c;
        float4 v = x[f4];
        float2 si = scale[f4 / 9];         // group = f4/9 (exact: 4 | 36)
        float scl = si.x, inv = si.y;
        __nv_bfloat16* sp = &s[ci * 65 + c * 4];
        sp[0] = __float2bfloat16_rn(rintf(v.x * inv) * scl);
        sp[1] = __float2bfloat16_rn(rintf(v.y * inv) * scl);
        sp[2] = __float2bfloat16_rn(rintf(v.z * inv) * scl);
        sp[3] = __float2bfloat16_rn(rintf(v.w * inv) * scl);
    }
    __syncthreads();
    #pragma unroll
    for (int it = 0; it < 2; ++it) {
        int idx = it * 256 + tid;          // [0,512)
        int pix = idx >> 3;
        int c   = idx & 7;
        uint4 v;
        __nv_bfloat16* e = (__nv_bfloat16*)&v;
        #pragma unroll
        for (int j = 0; j < 8; ++j) e[j] = s[(c * 8 + j) * 65 + pix];
        *(uint4*)(dst + ((size_t)(n * PIX + p0 + pix)) * 64 + c * 8) = v;
    }
}

// ---------------------------------------------------------------------------
// Weight repack: OIHW bf16 -> [k][co][ci]
// ---------------------------------------------------------------------------
__global__ void repack_w_kernel(const __nv_bfloat16* __restrict__ wq,
                                __nv_bfloat16* __restrict__ wk) {
    int gid = blockIdx.x * 256 + threadIdx.x;
    if (gid >= 9 * 64 * 64) return;
    int k  = gid >> 12;
    int r  = gid & 4095;
    int co = r >> 6;
    int ci = r & 63;
    wk[gid] = wq[co * 576 + ci * 9 + k];
}

// ---------------------------------------------------------------------------
// mma.sync / cp.async helpers
// ---------------------------------------------------------------------------
__device__ __forceinline__ void ldsm_x4(uint32_t& r0, uint32_t& r1,
                                        uint32_t& r2, uint32_t& r3,
                                        uint32_t addr) {
    asm volatile("ldmatrix.sync.aligned.m8n8.x4.shared.b16 {%0,%1,%2,%3}, [%4];"
                 : "=r"(r0), "=r"(r1), "=r"(r2), "=r"(r3) : "r"(addr));
}
__device__ __forceinline__ void mma_bf16(float* c, const uint32_t* a,
                                         uint32_t b0, uint32_t b1) {
    asm volatile(
        "mma.sync.aligned.m16n8k16.row.col.f32.bf16.bf16.f32 "
        "{%0,%1,%2,%3}, {%4,%5,%6,%7}, {%8,%9}, {%0,%1,%2,%3};"
        : "+f"(c[0]), "+f"(c[1]), "+f"(c[2]), "+f"(c[3])
        : "r"(a[0]), "r"(a[1]), "r"(a[2]), "r"(a[3]), "r"(b0), "r"(b1));
}
__device__ __forceinline__ uint32_t smem_u32(const void* p) {
    uint32_t a;
    asm("{ .reg .u64 t; cvta.to.shared.u64 t, %1; cvt.u32.u64 %0, t; }"
        : "=r"(a) : "l"(p));
    return a;
}
__device__ __forceinline__ void cp_async16(uint32_t dst, const void* src, bool pred) {
    int sz = pred ? 16 : 0;
    asm volatile("cp.async.cg.shared.global [%0], [%1], 16, %2;"
                 :: "r"(dst), "l"(src), "r"(sz) : "memory");
}
#define CP_COMMIT() asm volatile("cp.async.commit_group;" ::: "memory")
#define CP_WAIT(N)  asm volatile("cp.async.wait_group %0;" :: "n"(N) : "memory")

// ---------------------------------------------------------------------------
// Conv: halo-layout implicit GEMM, cp.async double-buffered.
// 128 threads / 4 warps. Warp tile = 32 pixels x ALL 64 co (maximizes MMA per
// smem byte: A 1KB + B 2KB -> 16 MMA per tap-chunk).
// A smem: [5 ih rows][114 w][64 ci], SW128. Tap (dh,dw) = row offset.
// SMEM: B 9x8192 | A0 73728 | A1 73728  -> 221184 bytes.
// ---------------------------------------------------------------------------
#define SMEM_B    0u
#define SMEM_A0   73728u
#define SMEM_A1   147456u
#define CONV_SMEM 221184u
#define A_STAGE_OPS 4560            // 5*114*8 x 16B

__global__ __launch_bounds__(128, 1)
void conv_mma_kernel(const __nv_bfloat16* __restrict__ xt,
                     const __nv_bfloat16* __restrict__ wk,
                     const float* __restrict__ bias,
                     float* __restrict__ out) {
    extern __shared__ char smem[];
    const uint32_t sb = smem_u32(smem);

    const int tid  = threadIdx.x;
    const int wid  = tid >> 5;         // 0..3 = m quadrant (32 pixels)
    const int lane = tid & 31;
    const int lrow = lane & 15;
    const int lcol = (lane >> 4) << 4; // 0 or 16 bytes
    const int g8   = lane >> 2;
    const int tg   = lane & 3;

    // Bias values for the 16 co columns this thread owns (8 nf x 2)
    float bv[8][2];
    #pragma unroll
    for (int nf = 0; nf < 8; ++nf) {
        int cob = nf * 8 + tg * 2;
        bv[nf][0] = bias[cob];
        bv[nf][1] = bias[cob + 1];
    }

    // Stage all 9 weight tiles (SW128 K-major: row=co, 128B of ci)
    for (int idx = tid; idx < 9 * 64 * 8; idx += 128) {
        int c  = idx & 7;
        int co = (idx >> 3) & 63;
        int k  = idx >> 9;
        uint4 v = *(const uint4*)(wk + ((k * 64 + co) * 64) + c * 8);
        *(uint4*)(smem + SMEM_B + k * 8192 + SW128((uint32_t)(co * 128 + c * 16))) = v;
    }

    // Stage one tile's input rows via cp.async (zfill OOB / w-borders)
    auto stage = [&](int t, uint32_t aoff) {
        const int n  = t / TILES_PER_IMG;
        const int p0 = (t - n * TILES_PER_IMG) * 128;
        const int hbase = p0 / WW - 1;
        const __nv_bfloat16* img = xt + (size_t)n * PIX * 64;
        #pragma unroll
        for (int it = 0; it < 36; ++it) {
            int idx = it * 128 + tid;
            if (idx < A_STAGE_OPS) {
                int c    = idx & 7;
                int rest = idx >> 3;           // 0..569
                int r    = rest / 114;
                int ws   = rest - r * 114;
                int ih   = hbase + r;
                int iw   = ws - 1;
                bool ok = ((unsigned)ih < (unsigned)HH) &
                          ((unsigned)iw < (unsigned)WW);
                const void* src = ok ? (const void*)(img + ((size_t)ih * WW + iw) * 64 + c * 8)
                                     : (const void*)img;
                cp_async16(sb + aoff + SW128((uint32_t)(rest * 128 + c * 16)), src, ok);
            }
        }
        CP_COMMIT();
    };

    int t = blockIdx.x;
    if (t < NTILES) stage(t, SMEM_A0);
    int pb = 0;

    for (; t < NTILES; t += gridDim.x, pb ^= 1) {
        const int n  = t / TILES_PER_IMG;
        const int p0 = (t - n * TILES_PER_IMG) * 128;
        const int oh0 = p0 / WW;
        const uint32_t ab = sb + (pb ? SMEM_A1 : SMEM_A0);

        const int tn = t + gridDim.x;
        if (tn < NTILES) {
            stage(tn, pb ? SMEM_A0 : SMEM_A1);
            CP_WAIT(1);
        } else {
            CP_WAIT(0);
        }
        __syncthreads();

        // Per-lane base rows in halo layout for the two m-fragments
        int browA[2];
        #pragma unroll
        for (int mf = 0; mf < 2; ++mf) {
            int p  = p0 + wid * 32 + mf * 16 + lrow;
            int oh = p / WW;
            int ow = p - oh * WW;
            browA[mf] = (oh - oh0 + 1) * 114 + ow + 1;
        }

        float acc[2][8][4];
        #pragma unroll
        for (int mf = 0; mf < 2; ++mf)
            #pragma unroll
            for (int nf = 0; nf < 8; ++nf)
                #pragma unroll
                for (int j = 0; j < 4; ++j) acc[mf][nf][j] = 0.f;

        #pragma unroll
        for (int kh = 0; kh < 3; ++kh) {
            #pragma unroll
            for (int kw = 0; kw < 3; ++kw) {
                const int k = kh * 3 + kw;
                const int shift = (kh - 1) * 114 + (kw - 1);
                #pragma unroll
                for (int s = 0; s < 4; ++s) {
                    const int cb = s * 32;
                    // B: all 64 co x 16 ci = 4 x LDSM.x4
                    uint32_t b[4][4];
                    #pragma unroll
                    for (int j = 0; j < 4; ++j)
                        ldsm_x4(b[j][0], b[j][1], b[j][2], b[j][3],
                                sb + SMEM_B + (uint32_t)k * 8192 +
                                SW128((uint32_t)((j * 16 + lrow) * 128 + cb + lcol)));
                    // A: 32 pixels x 16 ci = 2 x LDSM.x4
                    uint32_t a[2][4];
                    #pragma unroll
                    for (int mf = 0; mf < 2; ++mf) {
                        int row = browA[mf] + shift;
                        ldsm_x4(a[mf][0], a[mf][1], a[mf][2], a[mf][3],
                                ab + SW128((uint32_t)(row * 128 + cb + lcol)));
                    }
                    #pragma unroll
                    for (int mf = 0; mf < 2; ++mf)
                        #pragma unroll
                        for (int j = 0; j < 4; ++j) {
                            mma_bf16(acc[mf][2 * j],     a[mf], b[j][0], b[j][2]);
                            mma_bf16(acc[mf][2 * j + 1], a[mf], b[j][1], b[j][3]);
                        }
                }
            }
        }
        __syncthreads();   // all ldmatrix reads of buf pb done before restage

        // Epilogue: direct 32B-sector stores
        float* outN = out + (size_t)n * 64 * PIX + p0;
        #pragma unroll
        for (int mf = 0; mf < 2; ++mf) {
            const int pix = wid * 32 + mf * 16 + g8;
            #pragma unroll
            for (int nf = 0; nf < 8; ++nf) {
                const int cob = nf * 8 + tg * 2;
                float* r0 = outN + (size_t)cob * PIX;
                float* r1 = outN + (size_t)(cob + 1) * PIX;
                r0[pix]     = acc[mf][nf][0] + bv[nf][0];
                r1[pix]     = acc[mf][nf][1] + bv[nf][1];
                r0[pix + 8] = acc[mf][nf][2] + bv[nf][0];
                r1[pix + 8] = acc[mf][nf][3] + bv[nf][1];
            }
        }
    }
}

// ---------------------------------------------------------------------------
extern "C" void kernel_launch(void* const* d_in, const int* in_sizes, int n_in,
                              void* d_out, int out_size) {
    const float* x    = (const float*)d_in[0];
    const float* w    = (const float*)d_in[1];
    const float* bias = (const float*)d_in[2];
    float* out        = (float*)d_out;

    void *pxt, *pwq, *pwk, *psc;
    cudaGetSymbolAddress(&pxt, g_xt);
    cudaGetSymbolAddress(&pwq, g_wq);
    cudaGetSymbolAddress(&pwk, g_wk);
    cudaGetSymbolAddress(&psc, g_scale);
    __nv_bfloat16* xt = (__nv_bfloat16*)pxt;
    __nv_bfloat16* wq = (__nv_bfloat16*)pwq;
    __nv_bfloat16* wk = (__nv_bfloat16*)pwk;
    float2* scale     = (float2*)psc;

    const int n4x = NX / 4;          // 6,422,528
    const int n4w = NWELEM / 4;      // 9,216

    bfp_scale_kernel<<<(n4x + 2303) / 2304, 256>>>((const float4*)x, n4x,
                                                   NGROUPS, scale);
    bfp_quant_store_kernel<<<(n4w + 2303) / 2304, 256>>>((const float4*)w, n4w,
                                                         (uint2*)wq);
    quant_transpose_kernel<<<dim3(PIX / 64, N_BATCH), 256>>>((const float4*)x,
                                                             scale, xt);
    repack_w_kernel<<<(9 * 64 * 64 + 255) / 256, 256>>>(wq, wk);

    cudaFuncSetAttribute(conv_mma_kernel,
                         cudaFuncAttributeMaxDynamicSharedMemorySize,
                         CONV_SMEM);
    conv_mma_kernel<<<148, 128, CONV_SMEM>>>(xt, wk, bias, out);
}

// round 8
// speedup vs baseline: 1.0398x; 1.0398x over previous
#include <cuda_runtime.h>
#include <cuda_bf16.h>
#include <cstdint>

// ---------------------------------------------------------------------------
// Problem shape
// ---------------------------------------------------------------------------
#define N_BATCH 32
#define CH      64
#define HH      112
#define WW      112
#define PIX     (HH*WW)              // 12544
#define NX      (N_BATCH*CH*PIX)     // 25,690,112
#define NWELEM  (64*64*3*3)          // 36,864
#define TILES_PER_IMG (PIX/128)      // 98
#define NTILES  (N_BATCH*TILES_PER_IMG)  // 3136
#define NGROUPS ((NX + 35) / 36)     // 713,615

__device__ __align__(16) __nv_bfloat16 g_xt[NX];       // quantized x, NHWC
__device__ __align__(16) __nv_bfloat16 g_wq[NWELEM];   // quantized w, OIHW
__device__ __align__(16) __nv_bfloat16 g_wk[9*64*64];  // [k][co][ci]
__device__ __align__(16) float2        g_scale[NGROUPS]; // {scl, inv} per group

#define SW128(off) ((off) ^ (((off) >> 3) & 0x70))

// ---------------------------------------------------------------------------
// Pass 1 (x): per-group scale computation only.
// ---------------------------------------------------------------------------
__global__ __launch_bounds__(256)
void bfp_scale_kernel(const float4* __restrict__ src, int n4, long ngroups,
                      float2* __restrict__ scale) {
    __shared__ float sMax[2304];
    const int tid = threadIdx.x;
    const long base = (long)blockIdx.x * 2304;

    #pragma unroll
    for (int r = 0; r < 9; ++r) {
        long j = base + r * 256 + tid;
        float4 x = make_float4(0.f, 0.f, 0.f, 0.f);
        if (j < n4) x = src[j];
        sMax[r * 256 + tid] =
            fmaxf(fmaxf(fabsf(x.x), fabsf(x.y)), fmaxf(fabsf(x.z), fabsf(x.w)));
    }
    __syncthreads();
    long g = (long)blockIdx.x * 256 + tid;
    if (g < ngroups) {
        float m = sMax[tid * 9];
        #pragma unroll
        for (int i = 1; i < 9; ++i) m = fmaxf(m, sMax[tid * 9 + i]);
        float scl = 0.f, inv = 0.f;
        if (m > 0.f) {
            float e = floorf(log2f(m));
            scl = exp2f(e - 7.f);    // exact powers of two
            inv = exp2f(7.f - e);
        }
        scale[g] = make_float2(scl, inv);
    }
}

// ---------------------------------------------------------------------------
// Quantize with stores (weights only)
// ---------------------------------------------------------------------------
__global__ __launch_bounds__(256)
void bfp_quant_store_kernel(const float4* __restrict__ src, int n4,
                            uint2* __restrict__ dst) {
    __shared__ float sMax[2304];
    __shared__ float sScl[256];
    __shared__ float sInv[256];
    const int tid = threadIdx.x;
    const long base = (long)blockIdx.x * 2304;

    float4 v[9];
    #pragma unroll
    for (int r = 0; r < 9; ++r) {
        long j = base + r * 256 + tid;
        float4 x = make_float4(0.f, 0.f, 0.f, 0.f);
        if (j < n4) x = src[j];
        v[r] = x;
        sMax[r * 256 + tid] =
            fmaxf(fmaxf(fabsf(x.x), fabsf(x.y)), fmaxf(fabsf(x.z), fabsf(x.w)));
    }
    __syncthreads();
    {
        float m = sMax[tid * 9];
        #pragma unroll
        for (int i = 1; i < 9; ++i) m = fmaxf(m, sMax[tid * 9 + i]);
        float scl = 0.f, inv = 0.f;
        if (m > 0.f) {
            float e = floorf(log2f(m));
            scl = exp2f(e - 7.f);
            inv = exp2f(7.f - e);
        }
        sScl[tid] = scl;
        sInv[tid] = inv;
    }
    __syncthreads();
    #pragma unroll
    for (int r = 0; r < 9; ++r) {
        long j = base + r * 256 + tid;
        if (j >= n4) continue;
        int g = (r * 256 + tid) / 9;
        float scl = sScl[g], inv = sInv[g];
        float4 x = v[r];
        __nv_bfloat162 lo = __floats2bfloat162_rn(rintf(x.x * inv) * scl,
                                                  rintf(x.y * inv) * scl);
        __nv_bfloat162 hi = __floats2bfloat162_rn(rintf(x.z * inv) * scl,
                                                  rintf(x.w * inv) * scl);
        uint2 o;
        o.x = *(uint32_t*)&lo;
        o.y = *(uint32_t*)&hi;
        dst[j] = o;
    }
}

// ---------------------------------------------------------------------------
// Pass 2 (x): fused quantize + NCHW->NHWC transpose (scalar smem stores).
// ---------------------------------------------------------------------------
__global__ __launch_bounds__(256)
void quant_transpose_kernel(const float4* __restrict__ x,
                            const float2* __restrict__ scale,
                            __nv_bfloat16* __restrict__ dst) {
    __shared__ __nv_bfloat16 s[64 * 65];
    const int tid = threadIdx.x;
    const int n   = blockIdx.y;
    const int p0  = blockIdx.x * 64;

    #pragma unroll
    for (int it = 0; it < 4; ++it) {
        int idx = it * 256 + tid;
        int ci = idx >> 4;
        int c  = idx & 15;
        long f4 = (long)(n * 64 + ci) * (PIX / 4) + (p0 >> 2) + c;
        float4 v = x[f4];
        float2 si = scale[f4 / 9];
        float scl = si.x, inv = si.y;
        __nv_bfloat16* sp = &s[ci * 65 + c * 4];
        sp[0] = __float2bfloat16_rn(rintf(v.x * inv) * scl);
        sp[1] = __float2bfloat16_rn(rintf(v.y * inv) * scl);
        sp[2] = __float2bfloat16_rn(rintf(v.z * inv) * scl);
        sp[3] = __float2bfloat16_rn(rintf(v.w * inv) * scl);
    }
    __syncthreads();
    #pragma unroll
    for (int it = 0; it < 2; ++it) {
        int idx = it * 256 + tid;
        int pix = idx >> 3;
        int c   = idx & 7;
        uint4 v;
        __nv_bfloat16* e = (__nv_bfloat16*)&v;
        #pragma unroll
        for (int j = 0; j < 8; ++j) e[j] = s[(c * 8 + j) * 65 + pix];
        *(uint4*)(dst + ((size_t)(n * PIX + p0 + pix)) * 64 + c * 8) = v;
    }
}

// ---------------------------------------------------------------------------
// Weight repack: OIHW bf16 -> [k][co][ci]
// ---------------------------------------------------------------------------
__global__ void repack_w_kernel(const __nv_bfloat16* __restrict__ wq,
                                __nv_bfloat16* __restrict__ wk) {
    int gid = blockIdx.x * 256 + threadIdx.x;
    if (gid >= 9 * 64 * 64) return;
    int k  = gid >> 12;
    int r  = gid & 4095;
    int co = r >> 6;
    int ci = r & 63;
    wk[gid] = wq[co * 576 + ci * 9 + k];
}

// ---------------------------------------------------------------------------
// mma.sync / cp.async helpers
// ---------------------------------------------------------------------------
__device__ __forceinline__ void ldsm_x4(uint32_t& r0, uint32_t& r1,
                                        uint32_t& r2, uint32_t& r3,
                                        uint32_t addr) {
    asm volatile("ldmatrix.sync.aligned.m8n8.x4.shared.b16 {%0,%1,%2,%3}, [%4];"
                 : "=r"(r0), "=r"(r1), "=r"(r2), "=r"(r3) : "r"(addr));
}
__device__ __forceinline__ void mma_bf16(float* c, const uint32_t* a,
                                         uint32_t b0, uint32_t b1) {
    asm volatile(
        "mma.sync.aligned.m16n8k16.row.col.f32.bf16.bf16.f32 "
        "{%0,%1,%2,%3}, {%4,%5,%6,%7}, {%8,%9}, {%0,%1,%2,%3};"
        : "+f"(c[0]), "+f"(c[1]), "+f"(c[2]), "+f"(c[3])
        : "r"(a[0]), "r"(a[1]), "r"(a[2]), "r"(a[3]), "r"(b0), "r"(b1));
}
__device__ __forceinline__ uint32_t smem_u32(const void* p) {
    uint32_t a;
    asm("{ .reg .u64 t; cvta.to.shared.u64 t, %1; cvt.u32.u64 %0, t; }"
        : "=r"(a) : "l"(p));
    return a;
}
__device__ __forceinline__ void cp_async16(uint32_t dst, const void* src, bool pred) {
    int sz = pred ? 16 : 0;
    asm volatile("cp.async.cg.shared.global [%0], [%1], 16, %2;"
                 :: "r"(dst), "l"(src), "r"(sz) : "memory");
}
#define CP_COMMIT() asm volatile("cp.async.commit_group;" ::: "memory")
#define CP_WAIT(N)  asm volatile("cp.async.wait_group %0;" :: "n"(N) : "memory")

// ---------------------------------------------------------------------------
// Conv: halo-layout implicit GEMM, cp.async double-buffered.
// 256 threads / 8 warps (2 per SMSP for latency hiding).
// Warp tile = 32 pixels x 32 co: wm = wid&3 (pixel quarter), wc = wid>>2
// (co half). Per tap-chunk per warp: 2 A + 2 B LDSM.x4 -> 8 HMMA.
// Per-tile LDS = 590 KB ~= HMMA issue floor -> balanced pipes.
// SMEM: B 9x8192 | A0 73728 | A1 73728  -> 221184 bytes.
// ---------------------------------------------------------------------------
#define SMEM_B    0u
#define SMEM_A0   73728u
#define SMEM_A1   147456u
#define CONV_SMEM 221184u
#define A_STAGE_OPS 4560            // 5*114*8 x 16B

__global__ __launch_bounds__(256, 1)
void conv_mma_kernel(const __nv_bfloat16* __restrict__ xt,
                     const __nv_bfloat16* __restrict__ wk,
                     const float* __restrict__ bias,
                     float* __restrict__ out) {
    extern __shared__ char smem[];
    const uint32_t sb = smem_u32(smem);

    const int tid  = threadIdx.x;
    const int wid  = tid >> 5;
    const int lane = tid & 31;
    const int wm   = wid & 3;          // pixel quarter (32 px)
    const int wc   = wid >> 2;         // co half (32 co)
    const int lrow = lane & 15;
    const int lcol = (lane >> 4) << 4; // 0 or 16 bytes
    const int g8   = lane >> 2;
    const int tg   = lane & 3;

    // Bias for the 8 co columns this thread owns (4 nf x 2)
    float bv[4][2];
    #pragma unroll
    for (int nf = 0; nf < 4; ++nf) {
        int cob = wc * 32 + nf * 8 + tg * 2;
        bv[nf][0] = bias[cob];
        bv[nf][1] = bias[cob + 1];
    }

    // Stage all 9 weight tiles (SW128 K-major: row=co, 128B of ci)
    for (int idx = tid; idx < 9 * 64 * 8; idx += 256) {
        int c  = idx & 7;
        int co = (idx >> 3) & 63;
        int k  = idx >> 9;
        uint4 v = *(const uint4*)(wk + ((k * 64 + co) * 64) + c * 8);
        *(uint4*)(smem + SMEM_B + k * 8192 + SW128((uint32_t)(co * 128 + c * 16))) = v;
    }

    // Stage one tile's input rows via cp.async (zfill OOB / w-borders)
    auto stage = [&](int t, uint32_t aoff) {
        const int n  = t / TILES_PER_IMG;
        const int p0 = (t - n * TILES_PER_IMG) * 128;
        const int hbase = p0 / WW - 1;
        const __nv_bfloat16* img = xt + (size_t)n * PIX * 64;
        #pragma unroll
        for (int it = 0; it < 18; ++it) {
            int idx = it * 256 + tid;
            if (idx < A_STAGE_OPS) {
                int c    = idx & 7;
                int rest = idx >> 3;           // 0..569
                int r    = rest / 114;
                int ws   = rest - r * 114;
                int ih   = hbase + r;
                int iw   = ws - 1;
                bool ok = ((unsigned)ih < (unsigned)HH) &
                          ((unsigned)iw < (unsigned)WW);
                const void* src = ok ? (const void*)(img + ((size_t)ih * WW + iw) * 64 + c * 8)
                                     : (const void*)img;
                cp_async16(sb + aoff + SW128((uint32_t)(rest * 128 + c * 16)), src, ok);
            }
        }
        CP_COMMIT();
    };

    int t = blockIdx.x;
    if (t < NTILES) stage(t, SMEM_A0);
    int pb = 0;

    for (; t < NTILES; t += gridDim.x, pb ^= 1) {
        const int n  = t / TILES_PER_IMG;
        const int p0 = (t - n * TILES_PER_IMG) * 128;
        const int oh0 = p0 / WW;
        const uint32_t ab = sb + (pb ? SMEM_A1 : SMEM_A0);

        const int tn = t + gridDim.x;
        if (tn < NTILES) {
            stage(tn, pb ? SMEM_A0 : SMEM_A1);
            CP_WAIT(1);
        } else {
            CP_WAIT(0);
        }
        __syncthreads();

        // Per-lane base rows in halo layout for the two m-fragments
        int browA[2];
        #pragma unroll
        for (int mf = 0; mf < 2; ++mf) {
            int p  = p0 + wm * 32 + mf * 16 + lrow;
            int oh = p / WW;
            int ow = p - oh * WW;
            browA[mf] = (oh - oh0 + 1) * 114 + ow + 1;
        }

        float acc[2][4][4];
        #pragma unroll
        for (int mf = 0; mf < 2; ++mf)
            #pragma unroll
            for (int nf = 0; nf < 4; ++nf)
                #pragma unroll
                for (int j = 0; j < 4; ++j) acc[mf][nf][j] = 0.f;

        #pragma unroll
        for (int kh = 0; kh < 3; ++kh) {
            #pragma unroll
            for (int kw = 0; kw < 3; ++kw) {
                const int k = kh * 3 + kw;
                const int shift = (kh - 1) * 114 + (kw - 1);
                #pragma unroll
                for (int s = 0; s < 4; ++s) {
                    const int cb = s * 32;
                    // B: 32 co (this warp's half) x 16 ci = 2 x LDSM.x4
                    uint32_t b[2][4];
                    #pragma unroll
                    for (int j = 0; j < 2; ++j)
                        ldsm_x4(b[j][0], b[j][1], b[j][2], b[j][3],
                                sb + SMEM_B + (uint32_t)k * 8192 +
                                SW128((uint32_t)((wc * 32 + j * 16 + lrow) * 128 + cb + lcol)));
                    // A: 32 pixels x 16 ci = 2 x LDSM.x4
                    uint32_t a[2][4];
                    #pragma unroll
                    for (int mf = 0; mf < 2; ++mf) {
                        int row = browA[mf] + shift;
                        ldsm_x4(a[mf][0], a[mf][1], a[mf][2], a[mf][3],
                                ab + SW128((uint32_t)(row * 128 + cb + lcol)));
                    }
                    #pragma unroll
                    for (int mf = 0; mf < 2; ++mf)
                        #pragma unroll
                        for (int j = 0; j < 2; ++j) {
                            mma_bf16(acc[mf][2 * j],     a[mf], b[j][0], b[j][2]);
                            mma_bf16(acc[mf][2 * j + 1], a[mf], b[j][1], b[j][3]);
                        }
                }
            }
        }
        __syncthreads();   // all ldmatrix reads of buf pb done before restage

        // Epilogue: direct 32B-sector stores
        float* outN = out + (size_t)n * 64 * PIX + p0;
        #pragma unroll
        for (int mf = 0; mf < 2; ++mf) {
            const int pix = wm * 32 + mf * 16 + g8;
            #pragma unroll
            for (int nf = 0; nf < 4; ++nf) {
                const int cob = wc * 32 + nf * 8 + tg * 2;
                float* r0 = outN + (size_t)cob * PIX;
                float* r1 = outN + (size_t)(cob + 1) * PIX;
                r0[pix]     = acc[mf][nf][0] + bv[nf][0];
                r1[pix]     = acc[mf][nf][1] + bv[nf][1];
                r0[pix + 8] = acc[mf][nf][2] + bv[nf][0];
                r1[pix + 8] = acc[mf][nf][3] + bv[nf][1];
            }
        }
    }
}

// ---------------------------------------------------------------------------
extern "C" void kernel_launch(void* const* d_in, const int* in_sizes, int n_in,
                              void* d_out, int out_size) {
    const float* x    = (const float*)d_in[0];
    const float* w    = (const float*)d_in[1];
    const float* bias = (const float*)d_in[2];
    float* out        = (float*)d_out;

    void *pxt, *pwq, *pwk, *psc;
    cudaGetSymbolAddress(&pxt, g_xt);
    cudaGetSymbolAddress(&pwq, g_wq);
    cudaGetSymbolAddress(&pwk, g_wk);
    cudaGetSymbolAddress(&psc, g_scale);
    __nv_bfloat16* xt = (__nv_bfloat16*)pxt;
    __nv_bfloat16* wq = (__nv_bfloat16*)pwq;
    __nv_bfloat16* wk = (__nv_bfloat16*)pwk;
    float2* scale     = (float2*)psc;

    const int n4x = NX / 4;
    const int n4w = NWELEM / 4;

    bfp_scale_kernel<<<(n4x + 2303) / 2304, 256>>>((const float4*)x, n4x,
                                                   NGROUPS, scale);
    bfp_quant_store_kernel<<<(n4w + 2303) / 2304, 256>>>((const float4*)w, n4w,
                                                         (uint2*)wq);
    quant_transpose_kernel<<<dim3(PIX / 64, N_BATCH), 256>>>((const float4*)x,
                                                             scale, xt);
    repack_w_kernel<<<(9 * 64 * 64 + 255) / 256, 256>>>(wq, wk);

    cudaFuncSetAttribute(conv_mma_kernel,
                         cudaFuncAttributeMaxDynamicSharedMemorySize,
                         CONV_SMEM);
    conv_mma_kernel<<<148, 256, CONV_SMEM>>>(xt, wk, bias, out);
}